// round 9
// baseline (speedup 1.0000x reference)
#include <cuda_runtime.h>
#include <cuda_bf16.h>
#include <cstdint>
#include <cstddef>

// Problem constants
#define EMB   768
#define DK    256
#define DV    256
#define BB    8
#define NN    2048
#define HH    3
#define MALL  (BB*NN)          // 16384

typedef __nv_bfloat16 bf16;
typedef long long ll;

// ---------------------------------------------------------------------------
// Scratch (device globals — allocation is forbidden)
// ---------------------------------------------------------------------------
__device__ float g_V[HH * MALL * DV];              // fp32 V (pre-transpose)

__device__ bf16 g_xh[MALL * EMB],  g_xl[MALL * EMB];
__device__ bf16 g_Qh[HH * MALL * DK], g_Ql[HH * MALL * DK];
__device__ bf16 g_Kh[HH * MALL * DK], g_Kl[HH * MALL * DK];
__device__ bf16 g_Vth[HH * MALL * DV], g_Vtl[HH * MALL * DV];  // V^T [h][b][DV][NN]
__device__ bf16 g_Ch[MALL * HH * DV], g_Cl[MALL * HH * DV];    // concat hi/lo
__device__ bf16 g_Wqt[HH * DK * EMB], g_Wqtl[HH * DK * EMB];   // W^T [h][256][768]
__device__ bf16 g_Wkt[HH * DK * EMB], g_Wktl[HH * DK * EMB];
__device__ bf16 g_Wvt[HH * DV * EMB], g_Wvtl[HH * DV * EMB];
__device__ bf16 g_W0t[EMB * EMB],     g_W0tl[EMB * EMB];       // W0^T [768][768]

// ---------------------------------------------------------------------------
// PTX helpers (sm_80-compatible only: ldmatrix / mma.sync / cp.async)
// ---------------------------------------------------------------------------
__device__ __forceinline__ uint32_t smem_to_u32(const void* p) {
    uint32_t a;
    asm("{ .reg .u64 t; cvta.to.shared.u64 t, %1; cvt.u32.u64 %0, t; }" : "=r"(a) : "l"(p));
    return a;
}
__device__ __forceinline__ void ldsm4(uint32_t& r0, uint32_t& r1, uint32_t& r2,
                                      uint32_t& r3, uint32_t addr) {
    asm volatile("ldmatrix.sync.aligned.m8n8.x4.shared.b16 {%0,%1,%2,%3}, [%4];"
                 : "=r"(r0), "=r"(r1), "=r"(r2), "=r"(r3) : "r"(addr));
}
__device__ __forceinline__ void mma_bf16(float* d, const uint32_t* a, const uint32_t* b) {
    asm volatile("mma.sync.aligned.m16n8k16.row.col.f32.bf16.bf16.f32 "
                 "{%0,%1,%2,%3}, {%4,%5,%6,%7}, {%8,%9}, {%0,%1,%2,%3};"
                 : "+f"(d[0]), "+f"(d[1]), "+f"(d[2]), "+f"(d[3])
                 : "r"(a[0]), "r"(a[1]), "r"(a[2]), "r"(a[3]), "r"(b[0]), "r"(b[1]));
}
__device__ __forceinline__ void cpasync16(uint32_t dst, const void* src) {
    asm volatile("cp.async.cg.shared.global [%0], [%1], 16;" :: "r"(dst), "l"(src));
}
#define CP_COMMIT() asm volatile("cp.async.commit_group;" ::: "memory")
#define CP_WAIT(n)  asm volatile("cp.async.wait_group %0;" :: "n"(n) : "memory")

// ---------------------------------------------------------------------------
// Warp-MMA bf16 split GEMM (unchanged R7 winner): 128x128 tile, BK=32, 2 CTA/SM
// ---------------------------------------------------------------------------
#define RSB    80
#define TILEB  (128 * RSB)
#define STAGEB (4 * TILEB)
#define GSM    (2 * STAGEB)

template<int OMODE>
__global__ __launch_bounds__(256, 2)
void gemm_mma(const bf16* __restrict__ Ah, const bf16* __restrict__ Al,
              ll sA1, ll sA2,
              const bf16* __restrict__ Bh, const bf16* __restrict__ Bl,
              ll sB1, ll sB2,
              const float* __restrict__ bias, ll sb2,
              float* __restrict__ C, bf16* __restrict__ Coh, bf16* __restrict__ Col,
              int ldc, ll sC1, ll sC2,
              int Kdim, float alpha, int Z2)
{
    const int z  = blockIdx.z;
    const int z1 = z / Z2;
    const int z2 = z - z1 * Z2;
    Ah += z1 * sA1 + z2 * sA2;  Al += z1 * sA1 + z2 * sA2;
    Bh += z1 * sB1 + z2 * sB2;  Bl += z1 * sB1 + z2 * sB2;
    if (OMODE == 0) C += z1 * sC1 + z2 * sC2;
    else { Coh += z1 * sC1 + z2 * sC2; Col += z1 * sC1 + z2 * sC2; }
    const float* bptr = bias ? bias + z2 * sb2 : nullptr;

    const int m0 = blockIdx.y * 128;
    const int n0 = blockIdx.x * 128;

    extern __shared__ char smem[];
    const uint32_t sb = smem_to_u32(smem);
    const int tid  = threadIdx.x;
    const int wid  = tid >> 5;
    const int lane = tid & 31;
    const int wm   = wid >> 2;
    const int wn   = wid & 3;

    const int t  = tid >> 6;
    const int u  = tid & 63;
    const int lc = u & 3;
    const int lr = u >> 2;
    const bf16* tsrc = (t == 0) ? Ah : (t == 1) ? Al : (t == 2) ? Bh : Bl;
    const int rowbase = (t < 2) ? m0 : n0;
    const uint32_t dst0 = sb + (uint32_t)(t * TILEB) + (uint32_t)(lr * RSB + lc * 16);
    const int KT = Kdim >> 5;

    auto issue_loads = [&](int kt, int stage) {
        const bf16* src = tsrc + (size_t)(rowbase + lr) * Kdim + (kt << 5) + lc * 8;
        const size_t step = (size_t)16 * Kdim;
        uint32_t d = dst0 + stage * STAGEB;
#pragma unroll
        for (int j = 0; j < 8; j++) {
            cpasync16(d, src);
            d += 16 * RSB;
            src += step;
        }
        CP_COMMIT();
    };

    float acc[4][4][4];
#pragma unroll
    for (int i = 0; i < 4; i++)
#pragma unroll
        for (int j = 0; j < 4; j++)
#pragma unroll
            for (int q = 0; q < 4; q++) acc[i][j][q] = 0.f;

    issue_loads(0, 0);

    for (int kt = 0; kt < KT; kt++) {
        const int s = kt & 1;
        if (kt + 1 < KT) { issue_loads(kt + 1, s ^ 1); CP_WAIT(1); }
        else             { CP_WAIT(0); }
        __syncthreads();

        const uint32_t base = sb + s * STAGEB;
#pragma unroll
        for (int ks = 0; ks < 2; ks++) {
            const uint32_t colb = ks * 32 + (lane >> 4) * 16;
            const uint32_t arow = base + (uint32_t)(wm * 64 + (lane & 15)) * RSB + colb;
            const uint32_t brow = base + (uint32_t)(wn * 32 + (lane & 15)) * RSB + colb;

            uint32_t bh[4][2], bl[4][2];
#pragma unroll
            for (int nt2 = 0; nt2 < 2; nt2++) {
                uint32_t r0, r1, r2, r3;
                ldsm4(r0, r1, r2, r3, 2 * TILEB + brow + nt2 * 16 * RSB);
                bh[nt2 * 2 + 0][0] = r0; bh[nt2 * 2 + 0][1] = r2;
                bh[nt2 * 2 + 1][0] = r1; bh[nt2 * 2 + 1][1] = r3;
                ldsm4(r0, r1, r2, r3, 3 * TILEB + brow + nt2 * 16 * RSB);
                bl[nt2 * 2 + 0][0] = r0; bl[nt2 * 2 + 0][1] = r2;
                bl[nt2 * 2 + 1][0] = r1; bl[nt2 * 2 + 1][1] = r3;
            }
#pragma unroll
            for (int mt = 0; mt < 4; mt++) {
                uint32_t ah[4], al[4];
                ldsm4(ah[0], ah[1], ah[2], ah[3], 0 * TILEB + arow + mt * 16 * RSB);
                ldsm4(al[0], al[1], al[2], al[3], 1 * TILEB + arow + mt * 16 * RSB);
#pragma unroll
                for (int nt = 0; nt < 4; nt++) {
                    mma_bf16(acc[mt][nt], ah, bh[nt]);
                    mma_bf16(acc[mt][nt], ah, bl[nt]);
                    mma_bf16(acc[mt][nt], al, bh[nt]);
                }
            }
        }
        __syncthreads();
    }

#pragma unroll
    for (int mt = 0; mt < 4; mt++)
#pragma unroll
        for (int nt = 0; nt < 4; nt++) {
            const int row = m0 + wm * 64 + mt * 16 + (lane >> 2);
            const int col = n0 + wn * 32 + nt * 8 + (lane & 3) * 2;
            float b0v = 0.f, b1v = 0.f;
            if (bptr) { b0v = __ldg(bptr + col); b1v = __ldg(bptr + col + 1); }
#pragma unroll
            for (int h = 0; h < 2; h++) {
                const float v0 = acc[mt][nt][2 * h + 0] * alpha + b0v;
                const float v1 = acc[mt][nt][2 * h + 1] * alpha + b1v;
                const size_t off = (size_t)(row + 8 * h) * ldc + col;
                if (OMODE == 0) {
                    *(float2*)(C + off) = make_float2(v0, v1);
                } else {
                    const bf16 h0 = __float2bfloat16(v0);
                    const bf16 h1 = __float2bfloat16(v1);
                    *(__nv_bfloat162*)(Coh + off) = __nv_bfloat162(h0, h1);
                    *(__nv_bfloat162*)(Col + off) = __nv_bfloat162(
                        __float2bfloat16(v0 - __bfloat162float(h0)),
                        __float2bfloat16(v1 - __bfloat162float(h1)));
                }
            }
        }
}

// ---------------------------------------------------------------------------
// Flash attention: per CTA one 64-row Q block of one (h,b); online softmax
// over 16 KV blocks of 128. Split-bf16 3-pass for both QK^T and PV.
// Output: concat C hi/lo [b*N+n][h*256+dv].
// ---------------------------------------------------------------------------
#define QROWB 528               // 256 bf16 = 512B + 16 pad
#define KROWB 144               // 64 bf16 = 128B + 16 pad
#define VROWB 80                // 32 bf16 = 64B + 16 pad
#define PROWB 272               // 128 bf16 = 256B + 16 pad
#define SM_QH 0
#define SM_QL (64 * QROWB)                    // 33792
#define SM_U  (2 * 64 * QROWB)                // 67584 (union: K stages / V stages)
#define KSTG  (128 * KROWB)                   // 18432
#define VSTG  (256 * VROWB)                   // 20480
#define SM_PH (SM_U + 2 * 2 * VSTG)           // 149504
#define SM_PL (SM_PH + 64 * PROWB)            // 166912
#define SM_RED (SM_PL + 64 * PROWB)           // 184320
#define FLASH_SMEM (SM_RED + 4 * 64 * 4)      // 185344

__global__ __launch_bounds__(256, 1)
void flash_attn(const bf16* __restrict__ Qh, const bf16* __restrict__ Ql,
                const bf16* __restrict__ Kh, const bf16* __restrict__ Kl,
                const bf16* __restrict__ Vth, const bf16* __restrict__ Vtl,
                bf16* __restrict__ Coh, bf16* __restrict__ Col)
{
    const int z  = blockIdx.y;          // h*8 + b
    const int hh = z >> 3;
    const int b  = z & 7;
    const int q0 = blockIdx.x * 64;
    const ll qk_off = (ll)z * NN * DK;
    const ll v_off  = (ll)z * DV * NN;
    const bf16* Qhp = Qh + qk_off;
    const bf16* Qlp = Ql + qk_off;
    const bf16* Khp = Kh + qk_off;
    const bf16* Klp = Kl + qk_off;
    const bf16* Vhp = Vth + v_off;
    const bf16* Vlp = Vtl + v_off;

    extern __shared__ char smem[];
    const uint32_t sb = smem_to_u32(smem);
    float* red = (float*)(smem + SM_RED);   // [4][64]

    const int tid  = threadIdx.x;
    const int wid  = tid >> 5;
    const int lane = tid & 31;
    const int wm   = wid >> 2;          // 0..1  (m half)
    const int wn   = wid & 3;           // 0..3

    // ---- one-time Q block load: 64 rows x 256 bf16, hi+lo ----
    {
        const int row = tid >> 2, qt = tid & 3;
        const bf16* sh = Qhp + (size_t)(q0 + row) * DK + qt * 64;
        const bf16* sl = Qlp + (size_t)(q0 + row) * DK + qt * 64;
        uint32_t dh = sb + SM_QH + row * QROWB + qt * 128;
        uint32_t dl = sb + SM_QL + row * QROWB + qt * 128;
#pragma unroll
        for (int c = 0; c < 8; c++) {
            cpasync16(dh + c * 16, sh + c * 8);
            cpasync16(dl + c * 16, sl + c * 8);
        }
        CP_COMMIT();
    }

    // K-stage loader: 128 rows x 64 dk, hi+lo
    const int kl_row  = tid >> 1;
    const int kl_half = tid & 1;
    auto load_K = [&](int j, int kt, int stage) {
        const bf16* src = (kl_half ? Klp : Khp)
                        + (size_t)(j * 128 + kl_row) * DK + kt * 64;
        uint32_t d = sb + SM_U + stage * 2 * KSTG + kl_half * KSTG + kl_row * KROWB;
#pragma unroll
        for (int c = 0; c < 8; c++) cpasync16(d + c * 16, src + c * 8);
        CP_COMMIT();
    };
    // V-stage loader: 256 dv rows x 32 kv, hi+lo (one row per thread)
    auto load_V = [&](int j, int c, int stage) {
        const bf16* sh = Vhp + (size_t)tid * NN + j * 128 + c * 32;
        const bf16* sl = Vlp + (size_t)tid * NN + j * 128 + c * 32;
        uint32_t dh = sb + SM_U + stage * 2 * VSTG + tid * VROWB;
        uint32_t dl = dh + VSTG;
#pragma unroll
        for (int q = 0; q < 4; q++) {
            cpasync16(dh + q * 16, sh + q * 8);
            cpasync16(dl + q * 16, sl + q * 8);
        }
        CP_COMMIT();
    };

    float oacc[2][8][4];
#pragma unroll
    for (int i = 0; i < 2; i++)
#pragma unroll
        for (int j = 0; j < 8; j++)
#pragma unroll
            for (int q = 0; q < 4; q++) oacc[i][j][q] = 0.f;
    float m_st[4] = {-1e30f, -1e30f, -1e30f, -1e30f};
    float l_st[4] = {0.f, 0.f, 0.f, 0.f};

    for (int j = 0; j < 16; j++) {
        // ================= Phase 1: S = Q K^T (this KV block) =================
        float sacc[2][4][4];
#pragma unroll
        for (int i = 0; i < 2; i++)
#pragma unroll
            for (int n = 0; n < 4; n++)
#pragma unroll
                for (int q = 0; q < 4; q++) sacc[i][n][q] = 0.f;

        load_K(j, 0, 0);
        load_K(j, 1, 1);
        for (int kt = 0; kt < 4; kt++) {
            if (kt >= 1 && kt + 1 < 4) load_K(j, kt + 1, (kt + 1) & 1);
            if (kt + 1 < 4) CP_WAIT(1); else CP_WAIT(0);
            __syncthreads();
            const uint32_t kbH = sb + SM_U + (kt & 1) * 2 * KSTG;
            const uint32_t kbL = kbH + KSTG;
#pragma unroll
            for (int ks = 0; ks < 4; ks++) {
                const uint32_t qcolb = kt * 128 + ks * 32 + (lane >> 4) * 16;
                const uint32_t kcolb = ks * 32 + (lane >> 4) * 16;
                uint32_t bh[4][2], bl[4][2];
#pragma unroll
                for (int nt2 = 0; nt2 < 2; nt2++) {
                    uint32_t r0, r1, r2, r3;
                    ldsm4(r0, r1, r2, r3,
                          kbH + (uint32_t)(wn * 32 + nt2 * 16 + (lane & 15)) * KROWB + kcolb);
                    bh[nt2 * 2 + 0][0] = r0; bh[nt2 * 2 + 0][1] = r2;
                    bh[nt2 * 2 + 1][0] = r1; bh[nt2 * 2 + 1][1] = r3;
                    ldsm4(r0, r1, r2, r3,
                          kbL + (uint32_t)(wn * 32 + nt2 * 16 + (lane & 15)) * KROWB + kcolb);
                    bl[nt2 * 2 + 0][0] = r0; bl[nt2 * 2 + 0][1] = r2;
                    bl[nt2 * 2 + 1][0] = r1; bl[nt2 * 2 + 1][1] = r3;
                }
#pragma unroll
                for (int mt = 0; mt < 2; mt++) {
                    uint32_t ah[4], al[4];
                    ldsm4(ah[0], ah[1], ah[2], ah[3],
                          sb + SM_QH + (uint32_t)(wm * 32 + mt * 16 + (lane & 15)) * QROWB + qcolb);
                    ldsm4(al[0], al[1], al[2], al[3],
                          sb + SM_QL + (uint32_t)(wm * 32 + mt * 16 + (lane & 15)) * QROWB + qcolb);
#pragma unroll
                    for (int nt = 0; nt < 4; nt++) {
                        mma_bf16(sacc[mt][nt], ah, bh[nt]);
                        mma_bf16(sacc[mt][nt], ah, bl[nt]);
                        mma_bf16(sacc[mt][nt], al, bh[nt]);
                    }
                }
            }
            __syncthreads();
        }

        // ================= Prefetch V stages 0,1 (overlap softmax) ============
        load_V(j, 0, 0);
        load_V(j, 1, 1);

        // ================= Online softmax on S tile ==========================
#pragma unroll
        for (int mt = 0; mt < 2; mt++)
#pragma unroll
            for (int nt = 0; nt < 4; nt++)
#pragma unroll
                for (int q = 0; q < 4; q++) sacc[mt][nt][q] *= 0.0625f;

        // warp-local row max over 32 kv cols
#pragma unroll
        for (int mt = 0; mt < 2; mt++)
#pragma unroll
            for (int h = 0; h < 2; h++) {
                float v = sacc[mt][0][2 * h];
#pragma unroll
                for (int nt = 0; nt < 4; nt++) {
                    v = fmaxf(v, sacc[mt][nt][2 * h]);
                    v = fmaxf(v, sacc[mt][nt][2 * h + 1]);
                }
                v = fmaxf(v, __shfl_xor_sync(0xffffffffu, v, 1));
                v = fmaxf(v, __shfl_xor_sync(0xffffffffu, v, 2));
                if ((lane & 3) == 0)
                    red[wn * 64 + wm * 32 + mt * 16 + h * 8 + (lane >> 2)] = v;
            }
        __syncthreads();
        float mnew[2][2], corr[2][2];
#pragma unroll
        for (int mt = 0; mt < 2; mt++)
#pragma unroll
            for (int h = 0; h < 2; h++) {
                const int r = wm * 32 + mt * 16 + h * 8 + (lane >> 2);
                float bm = fmaxf(fmaxf(red[r], red[64 + r]),
                                 fmaxf(red[128 + r], red[192 + r]));
                const int idx = mt * 2 + h;
                const float mn = fmaxf(m_st[idx], bm);
                mnew[mt][h] = mn;
                corr[mt][h] = __expf(m_st[idx] - mn);
                m_st[idx] = mn;
            }
        __syncthreads();   // before reusing red for sums

        // exp, P->smem (bf16 hi/lo), warp-local row sums
#pragma unroll
        for (int mt = 0; mt < 2; mt++)
#pragma unroll
            for (int h = 0; h < 2; h++) {
                const float mn = mnew[mt][h];
                const int row = wm * 32 + mt * 16 + h * 8 + (lane >> 2);
                float s8 = 0.f;
#pragma unroll
                for (int nt = 0; nt < 4; nt++) {
                    const float p0 = __expf(sacc[mt][nt][2 * h] - mn);
                    const float p1 = __expf(sacc[mt][nt][2 * h + 1] - mn);
                    s8 += p0 + p1;
                    const int col = wn * 32 + nt * 8 + (lane & 3) * 2;
                    const bf16 h0 = __float2bfloat16(p0);
                    const bf16 h1 = __float2bfloat16(p1);
                    *(__nv_bfloat162*)(smem + SM_PH + row * PROWB + col * 2) =
                        __nv_bfloat162(h0, h1);
                    *(__nv_bfloat162*)(smem + SM_PL + row * PROWB + col * 2) =
                        __nv_bfloat162(__float2bfloat16(p0 - __bfloat162float(h0)),
                                       __float2bfloat16(p1 - __bfloat162float(h1)));
                }
                s8 += __shfl_xor_sync(0xffffffffu, s8, 1);
                s8 += __shfl_xor_sync(0xffffffffu, s8, 2);
                if ((lane & 3) == 0) red[wn * 64 + row] = s8;
            }
        __syncthreads();
#pragma unroll
        for (int mt = 0; mt < 2; mt++)
#pragma unroll
            for (int h = 0; h < 2; h++) {
                const int r = wm * 32 + mt * 16 + h * 8 + (lane >> 2);
                const float bs = red[r] + red[64 + r] + red[128 + r] + red[192 + r];
                const int idx = mt * 2 + h;
                l_st[idx] = l_st[idx] * corr[mt][h] + bs;
#pragma unroll
                for (int nt = 0; nt < 8; nt++) {
                    oacc[mt][nt][2 * h]     *= corr[mt][h];
                    oacc[mt][nt][2 * h + 1] *= corr[mt][h];
                }
            }

        // ================= Phase 2: O += P @ V^T-block =======================
        for (int c = 0; c < 4; c++) {
            if (c >= 1 && c + 1 < 4) load_V(j, c + 1, (c + 1) & 1);
            if (c + 1 < 4) CP_WAIT(1); else CP_WAIT(0);
            __syncthreads();
            const uint32_t vbH = sb + SM_U + (c & 1) * 2 * VSTG;
            const uint32_t vbL = vbH + VSTG;
#pragma unroll
            for (int ks = 0; ks < 2; ks++) {
                const uint32_t pcolb = c * 64 + ks * 32 + (lane >> 4) * 16;
                const uint32_t vcolb = ks * 32 + (lane >> 4) * 16;
                uint32_t vh[8][2], vl[8][2];
#pragma unroll
                for (int g = 0; g < 4; g++) {
                    uint32_t r0, r1, r2, r3;
                    ldsm4(r0, r1, r2, r3,
                          vbH + (uint32_t)(wn * 64 + g * 16 + (lane & 15)) * VROWB + vcolb);
                    vh[g * 2 + 0][0] = r0; vh[g * 2 + 0][1] = r2;
                    vh[g * 2 + 1][0] = r1; vh[g * 2 + 1][1] = r3;
                    ldsm4(r0, r1, r2, r3,
                          vbL + (uint32_t)(wn * 64 + g * 16 + (lane & 15)) * VROWB + vcolb);
                    vl[g * 2 + 0][0] = r0; vl[g * 2 + 0][1] = r2;
                    vl[g * 2 + 1][0] = r1; vl[g * 2 + 1][1] = r3;
                }
#pragma unroll
                for (int mt = 0; mt < 2; mt++) {
                    uint32_t ph[4], pl[4];
                    ldsm4(ph[0], ph[1], ph[2], ph[3],
                          sb + SM_PH + (uint32_t)(wm * 32 + mt * 16 + (lane & 15)) * PROWB + pcolb);
                    ldsm4(pl[0], pl[1], pl[2], pl[3],
                          sb + SM_PL + (uint32_t)(wm * 32 + mt * 16 + (lane & 15)) * PROWB + pcolb);
#pragma unroll
                    for (int nt = 0; nt < 8; nt++) {
                        mma_bf16(oacc[mt][nt], ph, vh[nt]);
                        mma_bf16(oacc[mt][nt], ph, vl[nt]);
                        mma_bf16(oacc[mt][nt], pl, vh[nt]);
                    }
                }
            }
            __syncthreads();
        }
    }

    // ================= Epilogue: O / l -> concat C hi/lo =====================
#pragma unroll
    for (int mt = 0; mt < 2; mt++)
#pragma unroll
        for (int h = 0; h < 2; h++) {
            const int idx = mt * 2 + h;
            const float inv = 1.0f / l_st[idx];
            const int r = wm * 32 + mt * 16 + h * 8 + (lane >> 2);
            const ll crow = ((ll)(b * NN + q0 + r)) * (HH * DV) + hh * DV;
#pragma unroll
            for (int nt = 0; nt < 8; nt++) {
                const int col = wn * 64 + nt * 8 + (lane & 3) * 2;
                const float v0 = oacc[mt][nt][2 * h] * inv;
                const float v1 = oacc[mt][nt][2 * h + 1] * inv;
                const bf16 h0 = __float2bfloat16(v0);
                const bf16 h1 = __float2bfloat16(v1);
                *(__nv_bfloat162*)(Coh + crow + col) = __nv_bfloat162(h0, h1);
                *(__nv_bfloat162*)(Col + crow + col) = __nv_bfloat162(
                    __float2bfloat16(v0 - __bfloat162float(h0)),
                    __float2bfloat16(v1 - __bfloat162float(h1)));
            }
        }
}

// ---------------------------------------------------------------------------
// fp32 -> (hi, lo) bf16 split, elementwise
// ---------------------------------------------------------------------------
__global__ void split4(const float* __restrict__ in, bf16* __restrict__ oh,
                       bf16* __restrict__ ol, int n4)
{
    const int i = blockIdx.x * blockDim.x + threadIdx.x;
    if (i >= n4) return;
    const float4 v = ((const float4*)in)[i];
    bf16 h0 = __float2bfloat16(v.x), h1 = __float2bfloat16(v.y);
    bf16 h2 = __float2bfloat16(v.z), h3 = __float2bfloat16(v.w);
    bf16 l0 = __float2bfloat16(v.x - __bfloat162float(h0));
    bf16 l1 = __float2bfloat16(v.y - __bfloat162float(h1));
    bf16 l2 = __float2bfloat16(v.z - __bfloat162float(h2));
    bf16 l3 = __float2bfloat16(v.w - __bfloat162float(h3));
    ((__nv_bfloat162*)oh)[2 * i + 0] = __nv_bfloat162(h0, h1);
    ((__nv_bfloat162*)oh)[2 * i + 1] = __nv_bfloat162(h2, h3);
    ((__nv_bfloat162*)ol)[2 * i + 0] = __nv_bfloat162(l0, l1);
    ((__nv_bfloat162*)ol)[2 * i + 1] = __nv_bfloat162(l2, l3);
}

// ---------------------------------------------------------------------------
// Batched transpose + split: in[R][Cc] fp32 -> out_hi/lo [Cc][R] bf16
// ---------------------------------------------------------------------------
__global__ void transpose_split(const float* __restrict__ in, bf16* __restrict__ oh,
                                bf16* __restrict__ ol, int R, int Cc,
                                ll sIn, ll sOut)
{
    __shared__ float tle[32][33];
    const int z = blockIdx.z;
    in += z * sIn;  oh += z * sOut;  ol += z * sOut;
    const int c0 = blockIdx.x * 32, r0 = blockIdx.y * 32;
    const int x = threadIdx.x, y = threadIdx.y;
#pragma unroll
    for (int i = 0; i < 32; i += 8)
        tle[y + i][x] = in[(size_t)(r0 + y + i) * Cc + c0 + x];
    __syncthreads();
#pragma unroll
    for (int i = 0; i < 32; i += 8) {
        const float v = tle[x][y + i];
        const bf16 h = __float2bfloat16(v);
        const size_t o = (size_t)(c0 + y + i) * R + r0 + x;
        oh[o] = h;
        ol[o] = __float2bfloat16(v - __bfloat162float(h));
    }
}

// ---------------------------------------------------------------------------
// Launch
// ---------------------------------------------------------------------------
extern "C" void kernel_launch(void* const* d_in, const int* in_sizes, int n_in,
                              void* d_out, int out_size)
{
    const float* x  = (const float*)d_in[0];
    const float* Wq = (const float*)d_in[1];
    const float* bq = (const float*)d_in[2];
    const float* Wk = (const float*)d_in[3];
    const float* bk = (const float*)d_in[4];
    const float* Wv = (const float*)d_in[5];
    const float* bv = (const float*)d_in[6];
    const float* W0 = (const float*)d_in[7];
    const float* b0 = (const float*)d_in[8];
    float* out = (float*)d_out;

    float *V;
    bf16 *xh, *xl, *Qh, *Ql, *Kh, *Kl, *Vth, *Vtl, *Ch, *Cl;
    bf16 *Wqt, *Wqtl, *Wkt, *Wktl, *Wvt, *Wvtl, *W0t, *W0tl;
    cudaGetSymbolAddress((void**)&V, g_V);
    cudaGetSymbolAddress((void**)&xh, g_xh);  cudaGetSymbolAddress((void**)&xl, g_xl);
    cudaGetSymbolAddress((void**)&Qh, g_Qh);  cudaGetSymbolAddress((void**)&Ql, g_Ql);
    cudaGetSymbolAddress((void**)&Kh, g_Kh);  cudaGetSymbolAddress((void**)&Kl, g_Kl);
    cudaGetSymbolAddress((void**)&Vth, g_Vth);cudaGetSymbolAddress((void**)&Vtl, g_Vtl);
    cudaGetSymbolAddress((void**)&Ch, g_Ch);  cudaGetSymbolAddress((void**)&Cl, g_Cl);
    cudaGetSymbolAddress((void**)&Wqt, g_Wqt);   cudaGetSymbolAddress((void**)&Wqtl, g_Wqtl);
    cudaGetSymbolAddress((void**)&Wkt, g_Wkt);   cudaGetSymbolAddress((void**)&Wktl, g_Wktl);
    cudaGetSymbolAddress((void**)&Wvt, g_Wvt);   cudaGetSymbolAddress((void**)&Wvtl, g_Wvtl);
    cudaGetSymbolAddress((void**)&W0t, g_W0t);   cudaGetSymbolAddress((void**)&W0tl, g_W0tl);

    cudaFuncSetAttribute(gemm_mma<0>, cudaFuncAttributeMaxDynamicSharedMemorySize, GSM);
    cudaFuncSetAttribute(gemm_mma<1>, cudaFuncAttributeMaxDynamicSharedMemorySize, GSM);
    cudaFuncSetAttribute(flash_attn, cudaFuncAttributeMaxDynamicSharedMemorySize, FLASH_SMEM);

    const dim3 tb(32, 8);

    // --- operand prep ---
    split4<<<(MALL * EMB / 4 + 255) / 256, 256>>>(x, xh, xl, MALL * EMB / 4);
    transpose_split<<<dim3(8, 24, 3), tb>>>(Wq, Wqt, Wqtl, EMB, DK,
                                            (ll)EMB * DK, (ll)EMB * DK);
    transpose_split<<<dim3(8, 24, 3), tb>>>(Wk, Wkt, Wktl, EMB, DK,
                                            (ll)EMB * DK, (ll)EMB * DK);
    transpose_split<<<dim3(8, 24, 3), tb>>>(Wv, Wvt, Wvtl, EMB, DV,
                                            (ll)EMB * DV, (ll)EMB * DV);
    transpose_split<<<dim3(24, 24, 1), tb>>>(W0, W0t, W0tl, EMB, EMB, 0, 0);

    // --- QKV projections ---
    {
        const dim3 g(DK / 128, MALL / 128, HH);
        gemm_mma<1><<<g, 256, GSM>>>(xh, xl, 0, 0,
                                     Wqt, Wqtl, 0, (ll)DK * EMB,
                                     bq, DK,
                                     nullptr, Qh, Ql, DK, 0, (ll)MALL * DK,
                                     EMB, 1.0f, HH);
        gemm_mma<1><<<g, 256, GSM>>>(xh, xl, 0, 0,
                                     Wkt, Wktl, 0, (ll)DK * EMB,
                                     bk, DK,
                                     nullptr, Kh, Kl, DK, 0, (ll)MALL * DK,
                                     EMB, 1.0f, HH);
        gemm_mma<0><<<g, 256, GSM>>>(xh, xl, 0, 0,
                                     Wvt, Wvtl, 0, (ll)DV * EMB,
                                     bv, DV,
                                     V, nullptr, nullptr, DV, 0, (ll)MALL * DV,
                                     EMB, 1.0f, HH);
    }

    // --- transpose+split V: [NN,DV] -> [DV,NN] per (h,b) ---
    transpose_split<<<dim3(DV / 32, NN / 32, HH * BB), tb>>>(
        V, Vth, Vtl, NN, DV, (ll)NN * DV, (ll)NN * DV);

    // --- fused attention: scores + softmax + PV -> concat hi/lo ---
    flash_attn<<<dim3(NN / 64, HH * BB), 256, FLASH_SMEM>>>(
        Qh, Ql, Kh, Kl, Vth, Vtl, Ch, Cl);

    // --- output projection: [16384,768] x [768,768]^T + b0 ---
    gemm_mma<0><<<dim3(EMB / 128, MALL / 128, 1), 256, GSM>>>(
        Ch, Cl, 0, 0,
        W0t, W0tl, 0, 0,
        b0, 0,
        out, nullptr, nullptr, EMB, 0, 0,
        HH * DV, 1.0f, 1);
}

// round 10
// speedup vs baseline: 1.4613x; 1.4613x over previous
#include <cuda_runtime.h>
#include <cuda_bf16.h>
#include <cstdint>
#include <cstddef>

// Problem constants
#define EMB   768
#define DK    256
#define DV    256
#define BB    8
#define NN    2048
#define HH    3
#define MALL  (BB*NN)          // 16384

typedef __nv_bfloat16 bf16;
typedef long long ll;

// ---------------------------------------------------------------------------
// Scratch (device globals — allocation is forbidden)
// ---------------------------------------------------------------------------
__device__ float g_S[(size_t)HH * BB * NN * NN];   // scores fp32 (402 MB)

__device__ bf16 g_xh[MALL * EMB],  g_xl[MALL * EMB];
__device__ bf16 g_Qh[HH * MALL * DK], g_Ql[HH * MALL * DK];
__device__ bf16 g_Kh[HH * MALL * DK], g_Kl[HH * MALL * DK];
__device__ bf16 g_Vth[HH * MALL * DV], g_Vtl[HH * MALL * DV];  // V^T [h][b][DV][NN]
__device__ bf16 g_Ph[(size_t)HH * BB * NN * NN], g_Pl[(size_t)HH * BB * NN * NN];
__device__ bf16 g_Ch[MALL * HH * DV], g_Cl[MALL * HH * DV];    // concat hi/lo
__device__ bf16 g_Wqt[HH * DK * EMB], g_Wqtl[HH * DK * EMB];   // W^T [h][256][768]
__device__ bf16 g_Wkt[HH * DK * EMB], g_Wktl[HH * DK * EMB];
__device__ bf16 g_Wvt[HH * DV * EMB], g_Wvtl[HH * DV * EMB];
__device__ bf16 g_W0t[EMB * EMB],     g_W0tl[EMB * EMB];       // W0^T [768][768]

// ---------------------------------------------------------------------------
// PTX helpers (sm_80-compatible only: ldmatrix / mma.sync / cp.async)
// ---------------------------------------------------------------------------
__device__ __forceinline__ uint32_t smem_to_u32(const void* p) {
    uint32_t a;
    asm("{ .reg .u64 t; cvta.to.shared.u64 t, %1; cvt.u32.u64 %0, t; }" : "=r"(a) : "l"(p));
    return a;
}
__device__ __forceinline__ void ldsm4(uint32_t& r0, uint32_t& r1, uint32_t& r2,
                                      uint32_t& r3, uint32_t addr) {
    asm volatile("ldmatrix.sync.aligned.m8n8.x4.shared.b16 {%0,%1,%2,%3}, [%4];"
                 : "=r"(r0), "=r"(r1), "=r"(r2), "=r"(r3) : "r"(addr));
}
__device__ __forceinline__ void mma_bf16(float* d, const uint32_t* a, const uint32_t* b) {
    asm volatile("mma.sync.aligned.m16n8k16.row.col.f32.bf16.bf16.f32 "
                 "{%0,%1,%2,%3}, {%4,%5,%6,%7}, {%8,%9}, {%0,%1,%2,%3};"
                 : "+f"(d[0]), "+f"(d[1]), "+f"(d[2]), "+f"(d[3])
                 : "r"(a[0]), "r"(a[1]), "r"(a[2]), "r"(a[3]), "r"(b[0]), "r"(b[1]));
}
__device__ __forceinline__ void cpasync16(uint32_t dst, const void* src) {
    asm volatile("cp.async.cg.shared.global [%0], [%1], 16;" :: "r"(dst), "l"(src));
}
#define CP_COMMIT() asm volatile("cp.async.commit_group;" ::: "memory")
#define CP_WAIT(n)  asm volatile("cp.async.wait_group %0;" :: "n"(n) : "memory")

// ---------------------------------------------------------------------------
// Warp-MMA bf16 split GEMM: C[m,n] = alpha * sum_k A[m,k]*B[n,k] (+ bias[n])
//   A: [Mrows,K] bf16 hi/lo K-major.  B: [Nrows,K] bf16 hi/lo K-major.
//   3-pass split accumulation (AhBh + AhBl + AlBh) in fp32 registers.
//   128x128 tile, BK=32, 256 threads, 3-stage cp.async, swizzled smem, 2 CTA/SM.
//   OMODE 0: fp32 C.
//   OMODE 1: bf16 hi/lo pair (Coh/Col), row-major ldc.
//   OMODE 2: bf16 hi/lo pair TRANSPOSED per batch: out[(m>>11)*DV + n][NN] + (m&2047)
// ---------------------------------------------------------------------------
// smem: rows of 64B (no pad), 16B-chunk swizzle: sc = c ^ ((row>>1)&3)
#define TILEB  (128 * 64)          // 8192
#define STAGEB (4 * TILEB)         // 32768: Ah, Al, Bh, Bl
#define NSTG   3
#define GSM    (NSTG * STAGEB)     // 98304 -> 2 CTAs/SM

template<int OMODE>
__global__ __launch_bounds__(256, 2)
void gemm_mma(const bf16* __restrict__ Ah, const bf16* __restrict__ Al,
              ll sA1, ll sA2,
              const bf16* __restrict__ Bh, const bf16* __restrict__ Bl,
              ll sB1, ll sB2,
              const float* __restrict__ bias, ll sb2,
              float* __restrict__ C, bf16* __restrict__ Coh, bf16* __restrict__ Col,
              int ldc, ll sC1, ll sC2,
              int Kdim, float alpha, int Z2)
{
    const int z  = blockIdx.z;
    const int z1 = z / Z2;
    const int z2 = z - z1 * Z2;
    Ah += z1 * sA1 + z2 * sA2;  Al += z1 * sA1 + z2 * sA2;
    Bh += z1 * sB1 + z2 * sB2;  Bl += z1 * sB1 + z2 * sB2;
    if (OMODE == 0) C += z1 * sC1 + z2 * sC2;
    else { Coh += z1 * sC1 + z2 * sC2; Col += z1 * sC1 + z2 * sC2; }
    const float* bptr = bias ? bias + z2 * sb2 : nullptr;

    const int m0 = blockIdx.y * 128;
    const int n0 = blockIdx.x * 128;

    extern __shared__ char smem[];
    const uint32_t sb = smem_to_u32(smem);
    const int tid  = threadIdx.x;
    const int wid  = tid >> 5;
    const int lane = tid & 31;
    const int wm   = wid >> 2;
    const int wn   = wid & 3;

    // ---- loader roles: 64 threads per tile (0:Ah 1:Al 2:Bh 3:Bl) ----
    const int t  = tid >> 6;
    const int u  = tid & 63;
    const int lc = u & 3;                  // 16B chunk in 64B row
    const int lr = u >> 2;                 // base row (step 16)
    const bf16* tsrc = (t == 0) ? Ah : (t == 1) ? Al : (t == 2) ? Bh : Bl;
    const int rowbase = (t < 2) ? m0 : n0;
    const int scw = lc ^ ((lr >> 1) & 3);  // swizzled chunk (constant per thread)
    const uint32_t dst0 = sb + (uint32_t)(t * TILEB + lr * 64 + scw * 16);
    const int KT = Kdim >> 5;

    auto issue_loads = [&](int kt, int stage) {
        const bf16* src = tsrc + (size_t)(rowbase + lr) * Kdim + (kt << 5) + lc * 8;
        const size_t step = (size_t)16 * Kdim;
        uint32_t d = dst0 + stage * STAGEB;
#pragma unroll
        for (int j = 0; j < 8; j++) {
            cpasync16(d, src);
            d += 16 * 64;
            src += step;
        }
        CP_COMMIT();
    };

    // ---- per-lane swizzled column offsets for ldmatrix (ks = 0, 1) ----
    const int l15 = lane & 15;
    const int lsw = (l15 >> 1) & 3;
    const uint32_t swk[2] = {
        (uint32_t)((((lane >> 4) + 0) ^ lsw) * 16),
        (uint32_t)((((lane >> 4) + 2) ^ lsw) * 16)
    };

    float acc[4][4][4];
#pragma unroll
    for (int i = 0; i < 4; i++)
#pragma unroll
        for (int j = 0; j < 4; j++)
#pragma unroll
            for (int q = 0; q < 4; q++) acc[i][j][q] = 0.f;

    issue_loads(0, 0);
    issue_loads(1, 1);

    int s = 0, s2 = 2;
    for (int kt = 0; kt < KT; kt++) {
        if (kt + 2 < KT) { issue_loads(kt + 2, s2); CP_WAIT(2); }
        else if (kt + 1 < KT) { CP_WAIT(1); }
        else { CP_WAIT(0); }
        __syncthreads();

        const uint32_t base = sb + s * STAGEB;
#pragma unroll
        for (int ks = 0; ks < 2; ks++) {
            const uint32_t arow = base + (uint32_t)((wm * 64 + l15) * 64) + swk[ks];
            const uint32_t brow = base + (uint32_t)((wn * 32 + l15) * 64) + swk[ks];

            uint32_t bh[4][2], bl[4][2];
#pragma unroll
            for (int nt2 = 0; nt2 < 2; nt2++) {
                uint32_t r0, r1, r2, r3;
                ldsm4(r0, r1, r2, r3, 2 * TILEB + brow + nt2 * 16 * 64);
                bh[nt2 * 2 + 0][0] = r0; bh[nt2 * 2 + 0][1] = r2;
                bh[nt2 * 2 + 1][0] = r1; bh[nt2 * 2 + 1][1] = r3;
                ldsm4(r0, r1, r2, r3, 3 * TILEB + brow + nt2 * 16 * 64);
                bl[nt2 * 2 + 0][0] = r0; bl[nt2 * 2 + 0][1] = r2;
                bl[nt2 * 2 + 1][0] = r1; bl[nt2 * 2 + 1][1] = r3;
            }
#pragma unroll
            for (int mt = 0; mt < 4; mt++) {
                uint32_t ah[4], al[4];
                ldsm4(ah[0], ah[1], ah[2], ah[3], 0 * TILEB + arow + mt * 16 * 64);
                ldsm4(al[0], al[1], al[2], al[3], 1 * TILEB + arow + mt * 16 * 64);
#pragma unroll
                for (int nt = 0; nt < 4; nt++) {
                    mma_bf16(acc[mt][nt], ah, bh[nt]);
                    mma_bf16(acc[mt][nt], ah, bl[nt]);
                    mma_bf16(acc[mt][nt], al, bh[nt]);
                }
            }
        }
        __syncthreads();
        s  = (s  == 2) ? 0 : s  + 1;
        s2 = (s2 == 2) ? 0 : s2 + 1;
    }

    // ---- epilogue ----
#pragma unroll
    for (int mt = 0; mt < 4; mt++)
#pragma unroll
        for (int nt = 0; nt < 4; nt++) {
            const int row0 = m0 + wm * 64 + mt * 16 + (lane >> 2);
            const int col  = n0 + wn * 32 + nt * 8 + (lane & 3) * 2;
            float b0v = 0.f, b1v = 0.f;
            if (bptr) { b0v = __ldg(bptr + col); b1v = __ldg(bptr + col + 1); }
#pragma unroll
            for (int h = 0; h < 2; h++) {
                const int row = row0 + 8 * h;
                const float v0 = acc[mt][nt][2 * h + 0] * alpha + b0v;
                const float v1 = acc[mt][nt][2 * h + 1] * alpha + b1v;
                if (OMODE == 0) {
                    *(float2*)(C + (size_t)row * ldc + col) = make_float2(v0, v1);
                } else if (OMODE == 1) {
                    const size_t off = (size_t)row * ldc + col;
                    const bf16 h0 = __float2bfloat16(v0);
                    const bf16 h1 = __float2bfloat16(v1);
                    *(__nv_bfloat162*)(Coh + off) = __nv_bfloat162(h0, h1);
                    *(__nv_bfloat162*)(Col + off) = __nv_bfloat162(
                        __float2bfloat16(v0 - __bfloat162float(h0)),
                        __float2bfloat16(v1 - __bfloat162float(h1)));
                } else {
                    // transposed hi/lo: out[((m>>11)*DV + n)*NN + (m&2047)]
                    const ll off = ((ll)(row >> 11) * DV + col) * NN + (row & (NN - 1));
                    const bf16 h0 = __float2bfloat16(v0);
                    const bf16 h1 = __float2bfloat16(v1);
                    Coh[off]      = h0;
                    Coh[off + NN] = h1;
                    Col[off]      = __float2bfloat16(v0 - __bfloat162float(h0));
                    Col[off + NN] = __float2bfloat16(v1 - __bfloat162float(h1));
                }
            }
        }
}

// ---------------------------------------------------------------------------
// fp32 -> (hi, lo) bf16 split, elementwise
// ---------------------------------------------------------------------------
__global__ void split4(const float* __restrict__ in, bf16* __restrict__ oh,
                       bf16* __restrict__ ol, int n4)
{
    const int i = blockIdx.x * blockDim.x + threadIdx.x;
    if (i >= n4) return;
    const float4 v = ((const float4*)in)[i];
    bf16 h0 = __float2bfloat16(v.x), h1 = __float2bfloat16(v.y);
    bf16 h2 = __float2bfloat16(v.z), h3 = __float2bfloat16(v.w);
    bf16 l0 = __float2bfloat16(v.x - __bfloat162float(h0));
    bf16 l1 = __float2bfloat16(v.y - __bfloat162float(h1));
    bf16 l2 = __float2bfloat16(v.z - __bfloat162float(h2));
    bf16 l3 = __float2bfloat16(v.w - __bfloat162float(h3));
    ((__nv_bfloat162*)oh)[2 * i + 0] = __nv_bfloat162(h0, h1);
    ((__nv_bfloat162*)oh)[2 * i + 1] = __nv_bfloat162(h2, h3);
    ((__nv_bfloat162*)ol)[2 * i + 0] = __nv_bfloat162(l0, l1);
    ((__nv_bfloat162*)ol)[2 * i + 1] = __nv_bfloat162(l2, l3);
}

// ---------------------------------------------------------------------------
// Batched transpose + split (weights only): in[R][Cc] fp32 -> out hi/lo [Cc][R]
// ---------------------------------------------------------------------------
__global__ void transpose_split(const float* __restrict__ in, bf16* __restrict__ oh,
                                bf16* __restrict__ ol, int R, int Cc,
                                ll sIn, ll sOut)
{
    __shared__ float tle[32][33];
    const int z = blockIdx.z;
    in += z * sIn;  oh += z * sOut;  ol += z * sOut;
    const int c0 = blockIdx.x * 32, r0 = blockIdx.y * 32;
    const int x = threadIdx.x, y = threadIdx.y;
#pragma unroll
    for (int i = 0; i < 32; i += 8)
        tle[y + i][x] = in[(size_t)(r0 + y + i) * Cc + c0 + x];
    __syncthreads();
#pragma unroll
    for (int i = 0; i < 32; i += 8) {
        const float v = tle[x][y + i];
        const bf16 h = __float2bfloat16(v);
        const size_t o = (size_t)(c0 + y + i) * R + r0 + x;
        oh[o] = h;
        ol[o] = __float2bfloat16(v - __bfloat162float(h));
    }
}

// ---------------------------------------------------------------------------
// Row softmax over 2048-wide rows -> bf16 hi/lo outputs
// ---------------------------------------------------------------------------
__global__ void softmax_split(const float* __restrict__ S, bf16* __restrict__ Ph,
                              bf16* __restrict__ Pl)
{
    const size_t row = (size_t)blockIdx.x * NN;
    const float* p = S + row;
    const int tid  = threadIdx.x;
    const int lane = tid & 31;
    const int warp = tid >> 5;
    __shared__ float red[8];

    float v[8];
#pragma unroll
    for (int i = 0; i < 8; i++) v[i] = p[tid + (i << 8)];

    float m = v[0];
#pragma unroll
    for (int i = 1; i < 8; i++) m = fmaxf(m, v[i]);
#pragma unroll
    for (int o = 16; o > 0; o >>= 1) m = fmaxf(m, __shfl_xor_sync(0xffffffffu, m, o));
    if (lane == 0) red[warp] = m;
    __syncthreads();
    if (warp == 0) {
        float tv = (lane < 8) ? red[lane] : -1e30f;
#pragma unroll
        for (int o = 16; o > 0; o >>= 1) tv = fmaxf(tv, __shfl_xor_sync(0xffffffffu, tv, o));
        if (lane == 0) red[0] = tv;
    }
    __syncthreads();
    m = red[0];
    __syncthreads();

    float s = 0.f;
#pragma unroll
    for (int i = 0; i < 8; i++) { v[i] = __expf(v[i] - m); s += v[i]; }
#pragma unroll
    for (int o = 16; o > 0; o >>= 1) s += __shfl_xor_sync(0xffffffffu, s, o);
    if (lane == 0) red[warp] = s;
    __syncthreads();
    if (warp == 0) {
        float tv = (lane < 8) ? red[lane] : 0.f;
#pragma unroll
        for (int o = 16; o > 0; o >>= 1) tv += __shfl_xor_sync(0xffffffffu, tv, o);
        if (lane == 0) red[0] = tv;
    }
    __syncthreads();
    const float inv = 1.0f / red[0];
#pragma unroll
    for (int i = 0; i < 8; i++) {
        const float w = v[i] * inv;
        const bf16 h = __float2bfloat16(w);
        const size_t o = row + tid + (i << 8);
        Ph[o] = h;
        Pl[o] = __float2bfloat16(w - __bfloat162float(h));
    }
}

// ---------------------------------------------------------------------------
// Launch
// ---------------------------------------------------------------------------
extern "C" void kernel_launch(void* const* d_in, const int* in_sizes, int n_in,
                              void* d_out, int out_size)
{
    const float* x  = (const float*)d_in[0];
    const float* Wq = (const float*)d_in[1];
    const float* bq = (const float*)d_in[2];
    const float* Wk = (const float*)d_in[3];
    const float* bk = (const float*)d_in[4];
    const float* Wv = (const float*)d_in[5];
    const float* bv = (const float*)d_in[6];
    const float* W0 = (const float*)d_in[7];
    const float* b0 = (const float*)d_in[8];
    float* out = (float*)d_out;

    float *S;
    bf16 *xh, *xl, *Qh, *Ql, *Kh, *Kl, *Vth, *Vtl, *Ph, *Pl, *Ch, *Cl;
    bf16 *Wqt, *Wqtl, *Wkt, *Wktl, *Wvt, *Wvtl, *W0t, *W0tl;
    cudaGetSymbolAddress((void**)&S, g_S);
    cudaGetSymbolAddress((void**)&xh, g_xh);  cudaGetSymbolAddress((void**)&xl, g_xl);
    cudaGetSymbolAddress((void**)&Qh, g_Qh);  cudaGetSymbolAddress((void**)&Ql, g_Ql);
    cudaGetSymbolAddress((void**)&Kh, g_Kh);  cudaGetSymbolAddress((void**)&Kl, g_Kl);
    cudaGetSymbolAddress((void**)&Vth, g_Vth);cudaGetSymbolAddress((void**)&Vtl, g_Vtl);
    cudaGetSymbolAddress((void**)&Ph, g_Ph);  cudaGetSymbolAddress((void**)&Pl, g_Pl);
    cudaGetSymbolAddress((void**)&Ch, g_Ch);  cudaGetSymbolAddress((void**)&Cl, g_Cl);
    cudaGetSymbolAddress((void**)&Wqt, g_Wqt);   cudaGetSymbolAddress((void**)&Wqtl, g_Wqtl);
    cudaGetSymbolAddress((void**)&Wkt, g_Wkt);   cudaGetSymbolAddress((void**)&Wktl, g_Wktl);
    cudaGetSymbolAddress((void**)&Wvt, g_Wvt);   cudaGetSymbolAddress((void**)&Wvtl, g_Wvtl);
    cudaGetSymbolAddress((void**)&W0t, g_W0t);   cudaGetSymbolAddress((void**)&W0tl, g_W0tl);

    cudaFuncSetAttribute(gemm_mma<0>, cudaFuncAttributeMaxDynamicSharedMemorySize, GSM);
    cudaFuncSetAttribute(gemm_mma<1>, cudaFuncAttributeMaxDynamicSharedMemorySize, GSM);
    cudaFuncSetAttribute(gemm_mma<2>, cudaFuncAttributeMaxDynamicSharedMemorySize, GSM);

    const dim3 tb(32, 8);

    // --- operand prep ---
    split4<<<(MALL * EMB / 4 + 255) / 256, 256>>>(x, xh, xl, MALL * EMB / 4);
    transpose_split<<<dim3(8, 24, 3), tb>>>(Wq, Wqt, Wqtl, EMB, DK,
                                            (ll)EMB * DK, (ll)EMB * DK);
    transpose_split<<<dim3(8, 24, 3), tb>>>(Wk, Wkt, Wktl, EMB, DK,
                                            (ll)EMB * DK, (ll)EMB * DK);
    transpose_split<<<dim3(8, 24, 3), tb>>>(Wv, Wvt, Wvtl, EMB, DV,
                                            (ll)EMB * DV, (ll)EMB * DV);
    transpose_split<<<dim3(24, 24, 1), tb>>>(W0, W0t, W0tl, EMB, EMB, 0, 0);

    // --- QKV projections: [16384,768] x [256,768]^T, batched over 3 heads ---
    {
        const dim3 g(DK / 128, MALL / 128, HH);
        // Q, K: row-major bf16 hi/lo
        gemm_mma<1><<<g, 256, GSM>>>(xh, xl, 0, 0,
                                     Wqt, Wqtl, 0, (ll)DK * EMB,
                                     bq, DK,
                                     nullptr, Qh, Ql, DK, 0, (ll)MALL * DK,
                                     EMB, 1.0f, HH);
        gemm_mma<1><<<g, 256, GSM>>>(xh, xl, 0, 0,
                                     Wkt, Wktl, 0, (ll)DK * EMB,
                                     bk, DK,
                                     nullptr, Kh, Kl, DK, 0, (ll)MALL * DK,
                                     EMB, 1.0f, HH);
        // V: transposed hi/lo directly into [h][b][DV][NN]
        gemm_mma<2><<<g, 256, GSM>>>(xh, xl, 0, 0,
                                     Wvt, Wvtl, 0, (ll)DV * EMB,
                                     bv, DV,
                                     nullptr, Vth, Vtl, 0, 0, (ll)BB * DV * NN,
                                     EMB, 1.0f, HH);
    }

    // --- scores: S = (Q K^T) / 16 over 24 (h,b) batches ---
    gemm_mma<0><<<dim3(NN / 128, NN / 128, HH * BB), 256, GSM>>>(
        Qh, Ql, (ll)MALL * DK, (ll)NN * DK,
        Kh, Kl, (ll)MALL * DK, (ll)NN * DK,
        nullptr, 0,
        S, nullptr, nullptr, NN, (ll)BB * NN * NN, (ll)NN * NN,
        DK, 0.0625f, BB);

    // --- softmax -> P hi/lo ---
    softmax_split<<<HH * BB * NN, 256>>>(S, Ph, Pl);

    // --- PV: O = P V into concat layout [b*N+n][h*256+d], bf16 hi/lo out ---
    gemm_mma<1><<<dim3(DV / 128, NN / 128, HH * BB), 256, GSM>>>(
        Ph, Pl, (ll)BB * NN * NN, (ll)NN * NN,
        Vth, Vtl, (ll)BB * DV * NN, (ll)DV * NN,
        nullptr, 0,
        nullptr, Ch, Cl, HH * DV, DV, (ll)NN * (HH * DV),
        NN, 1.0f, BB);

    // --- output projection: [16384,768] x [768,768]^T + b0 ---
    gemm_mma<0><<<dim3(EMB / 128, MALL / 128, 1), 256, GSM>>>(
        Ch, Cl, 0, 0,
        W0t, W0tl, 0, 0,
        b0, 0,
        out, nullptr, nullptr, EMB, 0, 0,
        HH * DV, 1.0f, 1);
}

// round 13
// speedup vs baseline: 1.4860x; 1.0169x over previous
#include <cuda_runtime.h>
#include <cuda_bf16.h>
#include <cstdint>
#include <cstddef>

// Problem constants
#define EMB   768
#define DK    256
#define DV    256
#define BB    8
#define NN    2048
#define HH    3
#define MALL  (BB*NN)          // 16384

typedef __nv_bfloat16 bf16;
typedef long long ll;

// ---------------------------------------------------------------------------
// Scratch (device globals — allocation is forbidden)
// ---------------------------------------------------------------------------
__device__ float g_rs[HH * BB * NN * 64];          // partial row sums of exp(S)

__device__ bf16 g_xh[MALL * EMB],  g_xl[MALL * EMB];
__device__ bf16 g_Qh[HH * MALL * DK], g_Ql[HH * MALL * DK];
__device__ bf16 g_Kh[HH * MALL * DK], g_Kl[HH * MALL * DK];
__device__ bf16 g_Vth[HH * MALL * DV], g_Vtl[HH * MALL * DV];  // V^T [h][b][DV][NN]
__device__ bf16 g_Ph[(size_t)HH * BB * NN * NN], g_Pl[(size_t)HH * BB * NN * NN];
__device__ bf16 g_Ch[MALL * HH * DV], g_Cl[MALL * HH * DV];    // concat hi/lo
__device__ bf16 g_Wqt[HH * DK * EMB], g_Wqtl[HH * DK * EMB];   // W^T [h][256][768]
__device__ bf16 g_Wkt[HH * DK * EMB], g_Wktl[HH * DK * EMB];
__device__ bf16 g_Wvt[HH * DV * EMB], g_Wvtl[HH * DV * EMB];
__device__ bf16 g_W0t[EMB * EMB],     g_W0tl[EMB * EMB];       // W0^T [768][768]

// ---------------------------------------------------------------------------
// PTX helpers (sm_80-compatible only: ldmatrix / mma.sync / cp.async)
// ---------------------------------------------------------------------------
__device__ __forceinline__ uint32_t smem_to_u32(const void* p) {
    uint32_t a;
    asm("{ .reg .u64 t; cvta.to.shared.u64 t, %1; cvt.u32.u64 %0, t; }" : "=r"(a) : "l"(p));
    return a;
}
__device__ __forceinline__ void ldsm4(uint32_t& r0, uint32_t& r1, uint32_t& r2,
                                      uint32_t& r3, uint32_t addr) {
    asm volatile("ldmatrix.sync.aligned.m8n8.x4.shared.b16 {%0,%1,%2,%3}, [%4];"
                 : "=r"(r0), "=r"(r1), "=r"(r2), "=r"(r3) : "r"(addr));
}
__device__ __forceinline__ void mma_bf16(float* d, const uint32_t* a, const uint32_t* b) {
    asm volatile("mma.sync.aligned.m16n8k16.row.col.f32.bf16.bf16.f32 "
                 "{%0,%1,%2,%3}, {%4,%5,%6,%7}, {%8,%9}, {%0,%1,%2,%3};"
                 : "+f"(d[0]), "+f"(d[1]), "+f"(d[2]), "+f"(d[3])
                 : "r"(a[0]), "r"(a[1]), "r"(a[2]), "r"(a[3]), "r"(b[0]), "r"(b[1]));
}
__device__ __forceinline__ void cpasync16(uint32_t dst, const void* src) {
    asm volatile("cp.async.cg.shared.global [%0], [%1], 16;" :: "r"(dst), "l"(src));
}
#define CP_COMMIT() asm volatile("cp.async.commit_group;" ::: "memory")
#define CP_WAIT(n)  asm volatile("cp.async.wait_group %0;" :: "n"(n) : "memory")

// ---------------------------------------------------------------------------
// Warp-MMA bf16 split GEMM: acc[m,n] = sum_k A[m,k]*B[n,k]
//   3-pass split accumulation (AhBh + AhBl + AlBh), fp32 registers.
//   128x128 tile, BK=32, 256 threads, 3-stage cp.async (1 barrier/kt),
//   swizzled smem, 2 CTA/SM.
//   OMODE 0: fp32 C = alpha*acc + bias.
//   OMODE 1: bf16 hi/lo (Coh/Col) = alpha*acc + bias, row-major ldc.
//   OMODE 2: bf16 hi/lo TRANSPOSED per batch: out[(m>>11)*DV + n][NN] + (m&2047)
//   OMODE 3: P = exp(alpha*acc) -> bf16 hi/lo + partial row sums to rs (via bias ptr)
//   OMODE 4: bf16 hi/lo = acc / rowsum(rs[row])  (rs via bias ptr)
// ---------------------------------------------------------------------------
// smem: rows of 64B (no pad), 16B-chunk swizzle: sc = c ^ ((row>>1)&3)
#define TILEB  (128 * 64)          // 8192
#define STAGEB (4 * TILEB)         // 32768: Ah, Al, Bh, Bl
#define NSTG   3
#define GSM    (NSTG * STAGEB)     // 98304 -> 2 CTAs/SM

template<int OMODE>
__global__ __launch_bounds__(256, 2)
void gemm_mma(const bf16* __restrict__ Ah, const bf16* __restrict__ Al,
              ll sA1, ll sA2,
              const bf16* __restrict__ Bh, const bf16* __restrict__ Bl,
              ll sB1, ll sB2,
              const float* __restrict__ bias, ll sb1, ll sb2,
              float* __restrict__ C, bf16* __restrict__ Coh, bf16* __restrict__ Col,
              int ldc, ll sC1, ll sC2,
              int Kdim, float alpha, int Z2)
{
    const int z  = blockIdx.z;
    const int z1 = z / Z2;
    const int z2 = z - z1 * Z2;
    Ah += z1 * sA1 + z2 * sA2;  Al += z1 * sA1 + z2 * sA2;
    Bh += z1 * sB1 + z2 * sB2;  Bl += z1 * sB1 + z2 * sB2;
    if (OMODE == 0) C += z1 * sC1 + z2 * sC2;
    else { Coh += z1 * sC1 + z2 * sC2; Col += z1 * sC1 + z2 * sC2; }
    const float* bptr = bias ? bias + z1 * sb1 + z2 * sb2 : nullptr;

    const int m0 = blockIdx.y * 128;
    const int n0 = blockIdx.x * 128;

    extern __shared__ char smem[];
    const uint32_t sb = smem_to_u32(smem);
    const int tid  = threadIdx.x;
    const int wid  = tid >> 5;
    const int lane = tid & 31;
    const int wm   = wid >> 2;
    const int wn   = wid & 3;

    // ---- loader roles: 64 threads per tile (0:Ah 1:Al 2:Bh 3:Bl) ----
    const int t  = tid >> 6;
    const int u  = tid & 63;
    const int lc = u & 3;
    const int lr = u >> 2;
    const bf16* tsrc = (t == 0) ? Ah : (t == 1) ? Al : (t == 2) ? Bh : Bl;
    const int rowbase = (t < 2) ? m0 : n0;
    const int scw = lc ^ ((lr >> 1) & 3);
    const uint32_t dst0 = sb + (uint32_t)(t * TILEB + lr * 64 + scw * 16);
    const int KT = Kdim >> 5;

    auto issue_loads = [&](int kt, int stage) {
        const bf16* src = tsrc + (size_t)(rowbase + lr) * Kdim + (kt << 5) + lc * 8;
        const size_t step = (size_t)16 * Kdim;
        uint32_t d = dst0 + stage * STAGEB;
#pragma unroll
        for (int j = 0; j < 8; j++) {
            cpasync16(d, src);
            d += 16 * 64;
            src += step;
        }
        CP_COMMIT();
    };

    const int l15 = lane & 15;
    const int lsw = (l15 >> 1) & 3;
    const uint32_t swk[2] = {
        (uint32_t)((((lane >> 4) + 0) ^ lsw) * 16),
        (uint32_t)((((lane >> 4) + 2) ^ lsw) * 16)
    };

    float acc[4][4][4];
#pragma unroll
    for (int i = 0; i < 4; i++)
#pragma unroll
        for (int j = 0; j < 4; j++)
#pragma unroll
            for (int q = 0; q < 4; q++) acc[i][j][q] = 0.f;

    issue_loads(0, 0);
    issue_loads(1, 1);

    int s = 0, s2 = 2;
    for (int kt = 0; kt < KT; kt++) {
        if (kt + 1 < KT) { CP_WAIT(1); } else { CP_WAIT(0); }
        __syncthreads();
        if (kt + 2 < KT) issue_loads(kt + 2, s2);   // writes stage all warps just freed

        const uint32_t base = sb + s * STAGEB;
#pragma unroll
        for (int ks = 0; ks < 2; ks++) {
            const uint32_t arow = base + (uint32_t)((wm * 64 + l15) * 64) + swk[ks];
            const uint32_t brow = base + (uint32_t)((wn * 32 + l15) * 64) + swk[ks];

            uint32_t bh[4][2], bl[4][2];
#pragma unroll
            for (int nt2 = 0; nt2 < 2; nt2++) {
                uint32_t r0, r1, r2, r3;
                ldsm4(r0, r1, r2, r3, 2 * TILEB + brow + nt2 * 16 * 64);
                bh[nt2 * 2 + 0][0] = r0; bh[nt2 * 2 + 0][1] = r2;
                bh[nt2 * 2 + 1][0] = r1; bh[nt2 * 2 + 1][1] = r3;
                ldsm4(r0, r1, r2, r3, 3 * TILEB + brow + nt2 * 16 * 64);
                bl[nt2 * 2 + 0][0] = r0; bl[nt2 * 2 + 0][1] = r2;
                bl[nt2 * 2 + 1][0] = r1; bl[nt2 * 2 + 1][1] = r3;
            }
#pragma unroll
            for (int mt = 0; mt < 4; mt++) {
                uint32_t ah[4], al[4];
                ldsm4(ah[0], ah[1], ah[2], ah[3], 0 * TILEB + arow + mt * 16 * 64);
                ldsm4(al[0], al[1], al[2], al[3], 1 * TILEB + arow + mt * 16 * 64);
#pragma unroll
                for (int nt = 0; nt < 4; nt++) {
                    mma_bf16(acc[mt][nt], ah, bh[nt]);
                    mma_bf16(acc[mt][nt], ah, bl[nt]);
                    mma_bf16(acc[mt][nt], al, bh[nt]);
                }
            }
        }
        s  = (s  == 2) ? 0 : s  + 1;
        s2 = (s2 == 2) ? 0 : s2 + 1;
    }

    // =========================== epilogues ===========================
    if (OMODE == 3) {
        // exp + P hi/lo + partial row sums (strip = blockIdx.x*4 + wn)
        float* rsw = (float*)bptr;
#pragma unroll
        for (int mt = 0; mt < 4; mt++)
#pragma unroll
            for (int h = 0; h < 2; h++) {
                const int row = m0 + wm * 64 + mt * 16 + h * 8 + (lane >> 2);
                float s8 = 0.f;
#pragma unroll
                for (int nt = 0; nt < 4; nt++) {
                    const float e0 = __expf(acc[mt][nt][2 * h + 0] * alpha);
                    const float e1 = __expf(acc[mt][nt][2 * h + 1] * alpha);
                    s8 += e0 + e1;
                    const int col = n0 + wn * 32 + nt * 8 + (lane & 3) * 2;
                    const size_t off = (size_t)row * ldc + col;
                    const bf16 h0 = __float2bfloat16(e0);
                    const bf16 h1 = __float2bfloat16(e1);
                    *(__nv_bfloat162*)(Coh + off) = __nv_bfloat162(h0, h1);
                    *(__nv_bfloat162*)(Col + off) = __nv_bfloat162(
                        __float2bfloat16(e0 - __bfloat162float(h0)),
                        __float2bfloat16(e1 - __bfloat162float(h1)));
                }
                s8 += __shfl_xor_sync(0xffffffffu, s8, 1);
                s8 += __shfl_xor_sync(0xffffffffu, s8, 2);
                if ((lane & 3) == 0)
                    rsw[(size_t)row * 64 + blockIdx.x * 4 + wn] = s8;
            }
        return;
    }

    float* sinv = (float*)smem;
    if (OMODE == 4) {
        // cooperative rowsum: 128 rows, 64 partials each
        __syncthreads();
        if (tid < 128) {
            const float4* p4 = (const float4*)(bptr + (size_t)(m0 + tid) * 64);
            float ssum = 0.f;
#pragma unroll
            for (int i = 0; i < 16; i++) {
                const float4 v = p4[i];
                ssum += v.x + v.y + v.z + v.w;
            }
            sinv[tid] = 1.0f / ssum;
        }
        __syncthreads();
    }

#pragma unroll
    for (int mt = 0; mt < 4; mt++)
#pragma unroll
        for (int nt = 0; nt < 4; nt++) {
            const int row0 = m0 + wm * 64 + mt * 16 + (lane >> 2);
            const int col  = n0 + wn * 32 + nt * 8 + (lane & 3) * 2;
            float b0v = 0.f, b1v = 0.f;
            if (bptr && OMODE <= 2) { b0v = __ldg(bptr + col); b1v = __ldg(bptr + col + 1); }
#pragma unroll
            for (int h = 0; h < 2; h++) {
                const int row = row0 + 8 * h;
                float sc = alpha;
                if (OMODE == 4) sc = sinv[row - m0];
                const float v0 = acc[mt][nt][2 * h + 0] * sc + b0v;
                const float v1 = acc[mt][nt][2 * h + 1] * sc + b1v;
                if (OMODE == 0) {
                    *(float2*)(C + (size_t)row * ldc + col) = make_float2(v0, v1);
                } else if (OMODE == 1 || OMODE == 4) {
                    const size_t off = (size_t)row * ldc + col;
                    const bf16 h0 = __float2bfloat16(v0);
                    const bf16 h1 = __float2bfloat16(v1);
                    *(__nv_bfloat162*)(Coh + off) = __nv_bfloat162(h0, h1);
                    *(__nv_bfloat162*)(Col + off) = __nv_bfloat162(
                        __float2bfloat16(v0 - __bfloat162float(h0)),
                        __float2bfloat16(v1 - __bfloat162float(h1)));
                } else {
                    const ll off = ((ll)(row >> 11) * DV + col) * NN + (row & (NN - 1));
                    const bf16 h0 = __float2bfloat16(v0);
                    const bf16 h1 = __float2bfloat16(v1);
                    Coh[off]      = h0;
                    Coh[off + NN] = h1;
                    Col[off]      = __float2bfloat16(v0 - __bfloat162float(h0));
                    Col[off + NN] = __float2bfloat16(v1 - __bfloat162float(h1));
                }
            }
        }
}

// ---------------------------------------------------------------------------
// fp32 -> (hi, lo) bf16 split, elementwise
// ---------------------------------------------------------------------------
__global__ void split4(const float* __restrict__ in, bf16* __restrict__ oh,
                       bf16* __restrict__ ol, int n4)
{
    const int i = blockIdx.x * blockDim.x + threadIdx.x;
    if (i >= n4) return;
    const float4 v = ((const float4*)in)[i];
    bf16 h0 = __float2bfloat16(v.x), h1 = __float2bfloat16(v.y);
    bf16 h2 = __float2bfloat16(v.z), h3 = __float2bfloat16(v.w);
    bf16 l0 = __float2bfloat16(v.x - __bfloat162float(h0));
    bf16 l1 = __float2bfloat16(v.y - __bfloat162float(h1));
    bf16 l2 = __float2bfloat16(v.z - __bfloat162float(h2));
    bf16 l3 = __float2bfloat16(v.w - __bfloat162float(h3));
    ((__nv_bfloat162*)oh)[2 * i + 0] = __nv_bfloat162(h0, h1);
    ((__nv_bfloat162*)oh)[2 * i + 1] = __nv_bfloat162(h2, h3);
    ((__nv_bfloat162*)ol)[2 * i + 0] = __nv_bfloat162(l0, l1);
    ((__nv_bfloat162*)ol)[2 * i + 1] = __nv_bfloat162(l2, l3);
}

// ---------------------------------------------------------------------------
// Batched transpose + split (weights only): in[R][Cc] fp32 -> out hi/lo [Cc][R]
// ---------------------------------------------------------------------------
__global__ void transpose_split(const float* __restrict__ in, bf16* __restrict__ oh,
                                bf16* __restrict__ ol, int R, int Cc,
                                ll sIn, ll sOut)
{
    __shared__ float tle[32][33];
    const int z = blockIdx.z;
    in += z * sIn;  oh += z * sOut;  ol += z * sOut;
    const int c0 = blockIdx.x * 32, r0 = blockIdx.y * 32;
    const int x = threadIdx.x, y = threadIdx.y;
#pragma unroll
    for (int i = 0; i < 32; i += 8)
        tle[y + i][x] = in[(size_t)(r0 + y + i) * Cc + c0 + x];
    __syncthreads();
#pragma unroll
    for (int i = 0; i < 32; i += 8) {
        const float v = tle[x][y + i];
        const bf16 h = __float2bfloat16(v);
        const size_t o = (size_t)(c0 + y + i) * R + r0 + x;
        oh[o] = h;
        ol[o] = __float2bfloat16(v - __bfloat162float(h));
    }
}

// ---------------------------------------------------------------------------
// Launch
// ---------------------------------------------------------------------------
extern "C" void kernel_launch(void* const* d_in, const int* in_sizes, int n_in,
                              void* d_out, int out_size)
{
    const float* x  = (const float*)d_in[0];
    const float* Wq = (const float*)d_in[1];
    const float* bq = (const float*)d_in[2];
    const float* Wk = (const float*)d_in[3];
    const float* bk = (const float*)d_in[4];
    const float* Wv = (const float*)d_in[5];
    const float* bv = (const float*)d_in[6];
    const float* W0 = (const float*)d_in[7];
    const float* b0 = (const float*)d_in[8];
    float* out = (float*)d_out;

    float *rs;
    bf16 *xh, *xl, *Qh, *Ql, *Kh, *Kl, *Vth, *Vtl, *Ph, *Pl, *Ch, *Cl;
    bf16 *Wqt, *Wqtl, *Wkt, *Wktl, *Wvt, *Wvtl, *W0t, *W0tl;
    cudaGetSymbolAddress((void**)&rs, g_rs);
    cudaGetSymbolAddress((void**)&xh, g_xh);  cudaGetSymbolAddress((void**)&xl, g_xl);
    cudaGetSymbolAddress((void**)&Qh, g_Qh);  cudaGetSymbolAddress((void**)&Ql, g_Ql);
    cudaGetSymbolAddress((void**)&Kh, g_Kh);  cudaGetSymbolAddress((void**)&Kl, g_Kl);
    cudaGetSymbolAddress((void**)&Vth, g_Vth);cudaGetSymbolAddress((void**)&Vtl, g_Vtl);
    cudaGetSymbolAddress((void**)&Ph, g_Ph);  cudaGetSymbolAddress((void**)&Pl, g_Pl);
    cudaGetSymbolAddress((void**)&Ch, g_Ch);  cudaGetSymbolAddress((void**)&Cl, g_Cl);
    cudaGetSymbolAddress((void**)&Wqt, g_Wqt);   cudaGetSymbolAddress((void**)&Wqtl, g_Wqtl);
    cudaGetSymbolAddress((void**)&Wkt, g_Wkt);   cudaGetSymbolAddress((void**)&Wktl, g_Wktl);
    cudaGetSymbolAddress((void**)&Wvt, g_Wvt);   cudaGetSymbolAddress((void**)&Wvtl, g_Wvtl);
    cudaGetSymbolAddress((void**)&W0t, g_W0t);   cudaGetSymbolAddress((void**)&W0tl, g_W0tl);

    cudaFuncSetAttribute(gemm_mma<0>, cudaFuncAttributeMaxDynamicSharedMemorySize, GSM);
    cudaFuncSetAttribute(gemm_mma<1>, cudaFuncAttributeMaxDynamicSharedMemorySize, GSM);
    cudaFuncSetAttribute(gemm_mma<2>, cudaFuncAttributeMaxDynamicSharedMemorySize, GSM);
    cudaFuncSetAttribute(gemm_mma<3>, cudaFuncAttributeMaxDynamicSharedMemorySize, GSM);
    cudaFuncSetAttribute(gemm_mma<4>, cudaFuncAttributeMaxDynamicSharedMemorySize, GSM);

    const dim3 tb(32, 8);

    // --- operand prep ---
    split4<<<(MALL * EMB / 4 + 255) / 256, 256>>>(x, xh, xl, MALL * EMB / 4);
    transpose_split<<<dim3(8, 24, 3), tb>>>(Wq, Wqt, Wqtl, EMB, DK,
                                            (ll)EMB * DK, (ll)EMB * DK);
    transpose_split<<<dim3(8, 24, 3), tb>>>(Wk, Wkt, Wktl, EMB, DK,
                                            (ll)EMB * DK, (ll)EMB * DK);
    transpose_split<<<dim3(8, 24, 3), tb>>>(Wv, Wvt, Wvtl, EMB, DV,
                                            (ll)EMB * DV, (ll)EMB * DV);
    transpose_split<<<dim3(24, 24, 1), tb>>>(W0, W0t, W0tl, EMB, EMB, 0, 0);

    // --- QKV projections: [16384,768] x [256,768]^T, batched over 3 heads ---
    {
        const dim3 g(DK / 128, MALL / 128, HH);
        gemm_mma<1><<<g, 256, GSM>>>(xh, xl, 0, 0,
                                     Wqt, Wqtl, 0, (ll)DK * EMB,
                                     bq, 0, DK,
                                     nullptr, Qh, Ql, DK, 0, (ll)MALL * DK,
                                     EMB, 1.0f, HH);
        gemm_mma<1><<<g, 256, GSM>>>(xh, xl, 0, 0,
                                     Wkt, Wktl, 0, (ll)DK * EMB,
                                     bk, 0, DK,
                                     nullptr, Kh, Kl, DK, 0, (ll)MALL * DK,
                                     EMB, 1.0f, HH);
        gemm_mma<2><<<g, 256, GSM>>>(xh, xl, 0, 0,
                                     Wvt, Wvtl, 0, (ll)DV * EMB,
                                     bv, 0, DV,
                                     nullptr, Vth, Vtl, 0, 0, (ll)BB * DV * NN,
                                     EMB, 1.0f, HH);
    }

    // --- scores+exp: P = exp(Q K^T / 16) hi/lo + partial row sums, 24 batches ---
    gemm_mma<3><<<dim3(NN / 128, NN / 128, HH * BB), 256, GSM>>>(
        Qh, Ql, (ll)MALL * DK, (ll)NN * DK,
        Kh, Kl, (ll)MALL * DK, (ll)NN * DK,
        rs, (ll)BB * NN * 64, (ll)NN * 64,
        nullptr, Ph, Pl, NN, (ll)BB * NN * NN, (ll)NN * NN,
        DK, 0.0625f, BB);

    // --- PV: O = (P V) / rowsum into concat layout, bf16 hi/lo out ---
    gemm_mma<4><<<dim3(DV / 128, NN / 128, HH * BB), 256, GSM>>>(
        Ph, Pl, (ll)BB * NN * NN, (ll)NN * NN,
        Vth, Vtl, (ll)BB * DV * NN, (ll)DV * NN,
        rs, (ll)BB * NN * 64, (ll)NN * 64,
        nullptr, Ch, Cl, HH * DV, DV, (ll)NN * (HH * DV),
        NN, 1.0f, BB);

    // --- output projection: [16384,768] x [768,768]^T + b0 ---
    gemm_mma<0><<<dim3(EMB / 128, MALL / 128, 1), 256, GSM>>>(
        Ch, Cl, 0, 0,
        W0t, W0tl, 0, 0,
        b0, 0, 0,
        out, nullptr, nullptr, EMB, 0, 0,
        HH * DV, 1.0f, 1);
}